// round 9
// baseline (speedup 1.0000x reference)
#include <cuda_runtime.h>
#include <cstdint>
#include <cstddef>

// Problem constants
#define NB   512
#define NT   2048
#define NXD  32
#define NUD  8
#define NYD  16
#define NH   128
#define NTHD 4
#define ZF_DIM 44   // NXD + NUD + NTHD
#define ZH_DIM 36   // NXD + NTHD

#define THREADS 128   // 1 batch row per block, 4 warps

// Exact XLA EmitFastTanh — bitwise-matched to the reference (verified rel_err=0).
__device__ __forceinline__ float xla_tanh(float x) {
    const float kClamp = 7.90531110763549805f;
    float ax = fabsf(x);
    float xc = fminf(fmaxf(x, -kClamp), kClamp);
    float x2 = __fmul_rn(xc, xc);
    float p;
    p = __fmaf_rn(x2, -2.76076847742355e-16f, 2.00018790482477e-13f);
    p = __fmaf_rn(x2, p, -8.60467152213735e-11f);
    p = __fmaf_rn(x2, p,  5.12229709037114e-08f);
    p = __fmaf_rn(x2, p,  1.48572235717979e-05f);
    p = __fmaf_rn(x2, p,  6.37261928875436e-04f);
    p = __fmaf_rn(x2, p,  4.89352455891786e-03f);
    p = __fmul_rn(xc, p);
    float q;
    q = __fmaf_rn(x2, 1.19825839466702e-06f, 1.18534705686654e-04f);
    q = __fmaf_rn(x2, q, 2.26843463243900e-03f);
    q = __fmaf_rn(x2, q, 4.89352518554385e-03f);
    float r = __fdiv_rn(p, q);
    return (ax < 0.0004f) ? x : r;
}

#define BAR_F2() asm volatile("bar.sync 1, 64;" ::: "memory")   // warps 0,1
#define BAR_HE() asm volatile("bar.sync 2, 64;" ::: "memory")   // warps 2,3 (epilogue)

__global__ void __launch_bounds__(THREADS, 4)
ssm_kernel(const float* __restrict__ x0g, const float* __restrict__ ug,
           const float* __restrict__ thfg, const float* __restrict__ thhg,
           const float* __restrict__ Wf1g, const float* __restrict__ bf1g,
           const float* __restrict__ Wf2g, const float* __restrict__ bf2g,
           const float* __restrict__ Wh1g, const float* __restrict__ bh1g,
           const float* __restrict__ Wh2g, const float* __restrict__ bh2g,
           const float* __restrict__ xming, const float* __restrict__ xmaxg,
           const float* __restrict__ yming, const float* __restrict__ ymaxg,
           float* __restrict__ outx, float* __restrict__ outy)
{
    __shared__ __align__(16) float WH2T[NYD * 132];   // WH2T[i*132+k] = Wh2[k][i]
    __shared__ __align__(16) float hf[NH], hh[NH];
    __shared__ __align__(16) float partial[32];
    __shared__ __align__(16) float zf0[48], zf1[48];  // [x(32)|u(8)|thf(4)|pad]
    __shared__ __align__(16) float zh0[48], zh1[48];  // [x_pre(32)|thh(4)|pad]
    __shared__ __align__(16) float bf2s[32];
    __shared__ __align__(16) float bh2s[16];
    __shared__ __align__(16) float consts[4];         // xlo xhi ylo yhi

    const int tt   = threadIdx.x;
    const int w    = tt >> 5;
    const int lane = tt & 31;
    const int b    = blockIdx.x;

    const float* ub  = ug   + (size_t)b * NT * NUD;
    float*       oxb = outx + (size_t)b * NT * NXD;
    float*       oyb = outy + (size_t)b * NT * NYD;

    // ---- register-resident weights ----
    // Every thread: one f1 column (unit tt): wF[k] = Wf1[k][tt]
    float wF[ZF_DIM];
#pragma unroll
    for (int k = 0; k < ZF_DIM; k++) wF[k] = Wf1g[k * NH + tt];
    const float bF = bf1g[tt];

    // wx union:
    //  warp0: f2 seg A weights  wx[k] = Wf2[k][lane],      k=0..63
    //  warp1: f2 seg B weights  wx[k] = Wf2[64+k][lane],   k=0..63
    //  warps2,3: two h1 columns wx[0..35]=Wh1[.][j], wx[36..71]=Wh1[.][j+64]
    float wx[72];
    float bH0 = 0.f, bH1 = 0.f;
    if (w == 0) {
#pragma unroll
        for (int k = 0; k < 64; k++) wx[k] = Wf2g[k * NXD + lane];
    } else if (w == 1) {
#pragma unroll
        for (int k = 0; k < 64; k++) wx[k] = Wf2g[(64 + k) * NXD + lane];
    } else {
        const int j = tt - 64;
#pragma unroll
        for (int k = 0; k < ZH_DIM; k++) {
            wx[k]      = Wh1g[k * NH + j];
            wx[36 + k] = Wh1g[k * NH + 64 + j];
        }
        bH0 = bh1g[j];
        bH1 = bh1g[tt];   // j + 64 == tt
    }

    // ---- smem staging ----
    for (int e = tt; e < NH * NYD; e += THREADS) {
        int k = e >> 4, i = e & 15;
        WH2T[i * 132 + k] = Wh2g[e];
    }
    if (tt < 32) bf2s[tt] = bf2g[tt];
    if (tt < 16) bh2s[tt] = bh2g[tt];
    if (tt == 0) {
        consts[0] = xming[0]; consts[1] = xmaxg[0];
        consts[2] = yming[0]; consts[3] = ymaxg[0];
    }
    if (tt < 32) {
        float xv = x0g[b * 32 + tt];
        zf0[tt] = xv;
        zh1[tt] = xv;          // h at t=0 reads zh1 (y0 = h(x_0))
        oxb[tt] = xv;          // x output index 0 is x_0
    }
    if (tt >= 32 && tt < 40) zf0[tt] = ub[tt - 32];                // u_0
    if (tt >= 40 && tt < 44) {
        float th = thfg[b * 4 + (tt - 40)];
        zf0[tt] = th; zf1[tt] = th;                                // theta_f both bufs
    }
    if (tt < 4) {
        float th = thhg[b * 4 + tt];
        zh0[32 + tt] = th; zh1[32 + tt] = th;                      // theta_h both bufs
    }
    __syncthreads();

    // ---- one simulation step (statically-resolved buffers via lambda) ----
    // zfc: f input (cur), zfn: f carry out (next), zhw: pre-clamp x out (h input
    // for NEXT iteration), zhr: h input for THIS iteration (prev step's zhw).
    auto step = [&](int t, const float* zfc, float* zfn, float* zhw, const float* zhr) {
        // ======== phase 1 ========
        float a0 = 0.f;
#pragma unroll
        for (int q = 0; q < ZF_DIM / 4; q++) {
            float4 z4 = *(const float4*)(zfc + 4 * q);
            a0 = __fmaf_rn(z4.x, wF[4 * q + 0], a0);
            a0 = __fmaf_rn(z4.y, wF[4 * q + 1], a0);
            a0 = __fmaf_rn(z4.z, wF[4 * q + 2], a0);
            a0 = __fmaf_rn(z4.w, wF[4 * q + 3], a0);
        }
        float ureg = 0.f;
        if (w == 1) {
            if (lane < 8) ureg = ub[(size_t)(t + 1) * NUD + lane];
            if (lane == 0 && t + 8 < NT)
                asm volatile("prefetch.global.L2 [%0];" :: "l"(ub + (size_t)(t + 8) * NUD));
        }
        if (w >= 2) {
            float b0 = 0.f, b1 = 0.f;
#pragma unroll
            for (int q = 0; q < ZH_DIM / 4; q++) {
                float4 z4 = *(const float4*)(zhr + 4 * q);
                b0 = __fmaf_rn(z4.x, wx[4 * q + 0], b0);
                b1 = __fmaf_rn(z4.x, wx[36 + 4 * q + 0], b1);
                b0 = __fmaf_rn(z4.y, wx[4 * q + 1], b0);
                b1 = __fmaf_rn(z4.y, wx[36 + 4 * q + 1], b1);
                b0 = __fmaf_rn(z4.z, wx[4 * q + 2], b0);
                b1 = __fmaf_rn(z4.z, wx[36 + 4 * q + 2], b1);
                b0 = __fmaf_rn(z4.w, wx[4 * q + 3], b0);
                b1 = __fmaf_rn(z4.w, wx[36 + 4 * q + 3], b1);
            }
            hh[tt - 64] = xla_tanh(__fadd_rn(b0, bH0));
            hh[tt]      = xla_tanh(__fadd_rn(b1, bH1));
        }
        hf[tt] = xla_tanh(__fadd_rn(a0, bF));
        __syncthreads();

        // ======== phase 2 ========
        if (w == 0) {
            // f2 segment A: ordered k = 0..63, register weights, broadcast hf
            float acc = 0.f;
#pragma unroll
            for (int q = 0; q < 16; q++) {
                float4 h4 = *(const float4*)(hf + 4 * q);
                acc = __fmaf_rn(h4.x, wx[4 * q + 0], acc);
                acc = __fmaf_rn(h4.y, wx[4 * q + 1], acc);
                acc = __fmaf_rn(h4.z, wx[4 * q + 2], acc);
                acc = __fmaf_rn(h4.w, wx[4 * q + 3], acc);
            }
            partial[lane] = acc;
            BAR_F2();
        } else if (w == 1) {
            BAR_F2();
            // f2 segment B: continue the SAME accumulator, k = 64..127
            float acc = partial[lane];
#pragma unroll
            for (int q = 0; q < 16; q++) {
                float4 h4 = *(const float4*)(hf + 64 + 4 * q);
                acc = __fmaf_rn(h4.x, wx[4 * q + 0], acc);
                acc = __fmaf_rn(h4.y, wx[4 * q + 1], acc);
                acc = __fmaf_rn(h4.z, wx[4 * q + 2], acc);
                acc = __fmaf_rn(h4.w, wx[4 * q + 3], acc);
            }
            float dx = __fadd_rn(acc, bf2s[lane]);
            float xn = __fadd_rn(zfc[lane], dx);     // pre-clamp x_new
            zhw[lane] = xn;                          // h input for next iteration
            float xc = fminf(fmaxf(xn, consts[0]), consts[1]);
            zfn[lane] = xc;                          // clamped carry
            oxb[(size_t)(t + 1) * NXD + lane] = xc;
            if (lane < 8) zfn[32 + lane] = ureg;     // stage u_{t+1}
        } else if (w == 2 && lane < 16) {
            // h2: strict 128-chain from smem (transposed, conflict-free .128)
            float acc = 0.f;
            const float* wr = WH2T + lane * 132;
#pragma unroll
            for (int q = 0; q < 32; q++) {
                float4 h4 = *(const float4*)(hh + 4 * q);
                float4 w4 = *(const float4*)(wr + 4 * q);
                acc = __fmaf_rn(h4.x, w4.x, acc);
                acc = __fmaf_rn(h4.y, w4.y, acc);
                acc = __fmaf_rn(h4.z, w4.z, acc);
                acc = __fmaf_rn(h4.w, w4.w, acc);
            }
            float y = __fadd_rn(acc, bh2s[lane]);
            if (t > 0) y = fminf(fmaxf(y, consts[2]), consts[3]);  // y0 unclamped
            oyb[(size_t)t * NYD + lane] = y;
        }
        __syncthreads();
    };

    // ---- main rollout: iterations t = 0 .. NT-2 (even/odd specialized) ----
    for (int t = 0; t < NT - 2; t += 2) {
        step(t,     zf0, zf1, zh0, zh1);
        step(t + 1, zf1, zf0, zh1, zh0);
    }
    step(NT - 2, zf0, zf1, zh0, zh1);   // t = 2046 (even)

    // ---- epilogue: h for the final state (written to zh0) -> y index NT-1 ----
    if (w >= 2) {
        float b0 = 0.f, b1 = 0.f;
#pragma unroll
        for (int q = 0; q < ZH_DIM / 4; q++) {
            float4 z4 = *(const float4*)(zh0 + 4 * q);
            b0 = __fmaf_rn(z4.x, wx[4 * q + 0], b0);
            b1 = __fmaf_rn(z4.x, wx[36 + 4 * q + 0], b1);
            b0 = __fmaf_rn(z4.y, wx[4 * q + 1], b0);
            b1 = __fmaf_rn(z4.y, wx[36 + 4 * q + 1], b1);
            b0 = __fmaf_rn(z4.z, wx[4 * q + 2], b0);
            b1 = __fmaf_rn(z4.z, wx[36 + 4 * q + 2], b1);
            b0 = __fmaf_rn(z4.w, wx[4 * q + 3], b0);
            b1 = __fmaf_rn(z4.w, wx[36 + 4 * q + 3], b1);
        }
        hh[tt - 64] = xla_tanh(__fadd_rn(b0, bH0));
        hh[tt]      = xla_tanh(__fadd_rn(b1, bH1));
        BAR_HE();
        if (w == 2 && lane < 16) {
            float acc = 0.f;
            const float* wr = WH2T + lane * 132;
#pragma unroll
            for (int q = 0; q < 32; q++) {
                float4 h4 = *(const float4*)(hh + 4 * q);
                float4 w4 = *(const float4*)(wr + 4 * q);
                acc = __fmaf_rn(h4.x, w4.x, acc);
                acc = __fmaf_rn(h4.y, w4.y, acc);
                acc = __fmaf_rn(h4.z, w4.z, acc);
                acc = __fmaf_rn(h4.w, w4.w, acc);
            }
            float y = __fadd_rn(acc, bh2s[lane]);
            y = fminf(fmaxf(y, consts[2]), consts[3]);
            oyb[(size_t)(NT - 1) * NYD + lane] = y;
        }
    }
}

extern "C" void kernel_launch(void* const* d_in, const int* in_sizes, int n_in,
                              void* d_out, int out_size) {
    (void)in_sizes; (void)n_in; (void)out_size;

    const float* x0   = (const float*)d_in[0];
    const float* u    = (const float*)d_in[1];
    const float* thf  = (const float*)d_in[2];
    const float* thh  = (const float*)d_in[3];
    const float* Wf1  = (const float*)d_in[4];
    const float* bf1  = (const float*)d_in[5];
    const float* Wf2  = (const float*)d_in[6];
    const float* bf2  = (const float*)d_in[7];
    const float* Wh1  = (const float*)d_in[8];
    const float* bh1  = (const float*)d_in[9];
    const float* Wh2  = (const float*)d_in[10];
    const float* bh2  = (const float*)d_in[11];
    const float* xmin = (const float*)d_in[12];
    const float* xmax = (const float*)d_in[13];
    const float* ymin = (const float*)d_in[14];
    const float* ymax = (const float*)d_in[15];

    float* outx = (float*)d_out;
    float* outy = outx + (size_t)NB * NT * NXD;

    ssm_kernel<<<NB, THREADS>>>(
        x0, u, thf, thh, Wf1, bf1, Wf2, bf2, Wh1, bh1, Wh2, bh2,
        xmin, xmax, ymin, ymax, outx, outy);
}